// round 8
// baseline (speedup 1.0000x reference)
#include <cuda_runtime.h>
#include <cstdint>

// CovNet_3058016715001 — binarized-weight MLP via int8 dual-plane mma.sync.
// Round 8: 24 warps/SM (3 CTAs x 256 thr, warp tile m16n32, 32 acc regs).
//   h   = clip(x @ sign(W1)^T + b1, -1, 1)     x:[8192,784] W1:[4096,784]
//   out = h @ W2^T + b2                        W2:[10,4096]  out:[8192,10]
//
// x -> Q = round(x*4096) = 256*Qh + Ql (two s8 planes); sign(W1) exact s8.
// Dual s32 accumulators; epilogue h = (256*accH + accL)/4096 + b1 -> clip
// -> fused fc2 -> atomicAdd (out pre-seeded with b2).

#define BATCH 8192
#define IN_F  784
#define KP8   832           // 13 * 64
#define HID   4096
#define NOUT  10

#define BM 32
#define BN 128
#define BK 64
#define NCH 13
#define NSTG 4

// stage layout: A_hi [32x64]=2K | A_lo 2K | B [128x64]=8K
#define OFF_ALO 2048
#define OFF_BW  4096
#define STAGE   12288

// dynamic smem map (128-aligned base):
//   [0, 49152)       4 stages
//   [49152, 54272)   W2s [10][128] f32
//   [54272, 54784)   b1s [128] f32
#define OFF_W2   49152
#define OFF_B1   54272
#define SMEM_REQ (54784 + 128)

#define SCALE_S 4096.0f
#define INV_S   (1.0f / 4096.0f)

static __device__ char g_Xh8[(size_t)BATCH * KP8];
static __device__ char g_Xl8[(size_t)BATCH * KP8];
static __device__ char g_W8 [(size_t)HID * KP8];

// ---------------------------------------------------------------- helpers
__device__ __forceinline__ uint32_t smem_u32(const void* p) {
    return (uint32_t)__cvta_generic_to_shared(p);
}

#define CP_ASYNC16(s, g) \
    asm volatile("cp.async.cg.shared.global [%0], [%1], 16;" :: "r"(s), "l"(g))
#define CP_COMMIT() asm volatile("cp.async.commit_group;")
#define CP_WAIT(n)  asm volatile("cp.async.wait_group %0;" :: "n"(n) : "memory")

__device__ __forceinline__ void ldm_x4(uint32_t& r0, uint32_t& r1, uint32_t& r2,
                                       uint32_t& r3, uint32_t addr) {
    asm volatile("ldmatrix.sync.aligned.m8n8.x4.shared.b16 {%0,%1,%2,%3}, [%4];"
                 : "=r"(r0), "=r"(r1), "=r"(r2), "=r"(r3) : "r"(addr));
}

#define MMA_S8(d, a, b) \
    asm volatile("mma.sync.aligned.m16n8k32.row.col.s32.s8.s8.s32 " \
        "{%0,%1,%2,%3}, {%4,%5,%6,%7}, {%8,%9}, {%0,%1,%2,%3};" \
        : "+r"((d)[0]), "+r"((d)[1]), "+r"((d)[2]), "+r"((d)[3]) \
        : "r"((a)[0]), "r"((a)[1]), "r"((a)[2]), "r"((a)[3]), \
          "r"((b)[0]), "r"((b)[1]))

__device__ __forceinline__ uint32_t sw128(uint32_t flat) {
    return flat ^ ((flat >> 3) & 0x70);
}

// ---------------------------------------------------------------- prep
__global__ void init_out_kernel(float* __restrict__ out, const float* __restrict__ b2) {
    int i = blockIdx.x * blockDim.x + threadIdx.x;
    if (i < BATCH * NOUT) out[i] = b2[i % NOUT];
}

__global__ void conv_x8_kernel(const float* __restrict__ X) {
    int idx = blockIdx.x * blockDim.x + threadIdx.x;
    if (idx >= BATCH * (KP8 / 4)) return;
    int r  = idx / (KP8 / 4);
    int c4 = (idx % (KP8 / 4)) * 4;
    char hq[4], lq[4];
    #pragma unroll
    for (int j = 0; j < 4; ++j) {
        int col = c4 + j;
        float x = (col < IN_F) ? X[(size_t)r * IN_F + col] : 0.0f;
        int Q = __float2int_rn(x * SCALE_S);
        Q = max(-32512, min(32512, Q));
        int Qh = (Q + 128) >> 8;
        int Ql = Q - (Qh << 8);
        hq[j] = (char)Qh;
        lq[j] = (char)Ql;
    }
    *(char4*)(g_Xh8 + (size_t)r * KP8 + c4) = make_char4(hq[0], hq[1], hq[2], hq[3]);
    *(char4*)(g_Xl8 + (size_t)r * KP8 + c4) = make_char4(lq[0], lq[1], lq[2], lq[3]);
}

__global__ void conv_w8_kernel(const float* __restrict__ W1) {
    int idx = blockIdx.x * blockDim.x + threadIdx.x;
    if (idx >= HID * (KP8 / 4)) return;
    int r  = idx / (KP8 / 4);
    int c4 = (idx % (KP8 / 4)) * 4;
    char s[4];
    #pragma unroll
    for (int j = 0; j < 4; ++j) {
        int col = c4 + j;
        char v = 0;
        if (col < IN_F) {
            float w = W1[(size_t)r * IN_F + col];
            v = (w > 0.0f) ? (char)1 : ((w < 0.0f) ? (char)-1 : (char)0);
        }
        s[j] = v;
    }
    *(char4*)(g_W8 + (size_t)r * KP8 + c4) = make_char4(s[0], s[1], s[2], s[3]);
}

// ---------------------------------------------------------------- main
__global__ void __launch_bounds__(256, 3) fused_i8_kernel(
    const float* __restrict__ b1, const float* __restrict__ W2,
    float* __restrict__ out)
{
    extern __shared__ char smem_raw[];
    const uint32_t rawA  = smem_u32(smem_raw);
    const uint32_t sbase = (rawA + 127) & ~127u;
    char* gbase = smem_raw + (sbase - rawA);
    float* W2s = (float*)(gbase + OFF_W2);
    float* b1s = (float*)(gbase + OFF_B1);

    const int tid  = threadIdx.x;
    const int lane = tid & 31;
    const int wid  = tid >> 5;
    const int wm   = wid & 1;        // 2 warp slots along M (16 rows each)
    const int wn   = wid >> 1;       // 4 warp slots along N (32 cols each)

    const int bm = blockIdx.y * BM;
    const int bn = blockIdx.x * BN;

    // ---- stage W2 / b1 slices (used only in epilogue) ----
    for (int i = tid; i < NOUT * BN; i += 256)
        W2s[i] = W2[(size_t)(i >> 7) * HID + bn + (i & 127)];
    if (tid < BN) b1s[tid] = b1[bn + tid];

    // ---- loader mapping ----
    // A planes: 32 rows x 4 segs x 2 planes = 256 chunks -> one per thread.
    // B plane: 128 rows x 4 segs = 512 chunks -> two per thread.
    const int aRowL = (tid & 127) >> 2;      // 0..31
    const int aSeg  = tid & 3;
    const uint32_t aPl  = (tid < 128) ? 0u : (uint32_t)OFF_ALO;
    const uint32_t aSw  = aPl + sw128((uint32_t)((tid & 127) * 16));
    const char* gXa = ((tid < 128) ? g_Xh8 : g_Xl8)
                      + (size_t)(bm + aRowL) * KP8 + aSeg * 16;
    const uint32_t bSw0 = sw128((uint32_t)tid * 16);
    const uint32_t bSw1 = sw128((uint32_t)tid * 16 + 4096);
    const char* gW0 = g_W8 + (size_t)(bn + (tid >> 2)) * KP8 + (tid & 3) * 16;
    const char* gW1 = g_W8 + (size_t)(bn + 64 + (tid >> 2)) * KP8 + (tid & 3) * 16;

    // ---- ldmatrix per-lane offsets (row stride 64 B, 2 k-steps) ----
    const int lg  = lane >> 3;
    const int lr8 = lane & 7;
    uint32_t aOff[2], bOff[2][2];
    {
        int r = wm * 16 + ((lg & 1) << 3) + lr8;
        #pragma unroll
        for (int ks = 0; ks < 2; ++ks)
            aOff[ks] = sw128((uint32_t)(r * 64 + ks * 32 + (lg >> 1) * 16));
    }
    #pragma unroll
    for (int n2 = 0; n2 < 2; ++n2) {
        int r = wn * 32 + n2 * 16 + (((lane >> 4) & 1) << 3) + lr8;
        #pragma unroll
        for (int ks = 0; ks < 2; ++ks)
            bOff[n2][ks] = sw128((uint32_t)(r * 64 + ks * 32 + (lg & 1) * 16));
    }

    int accH[4][4], accL[4][4];
    #pragma unroll
    for (int ni = 0; ni < 4; ++ni)
        #pragma unroll
        for (int q = 0; q < 4; ++q) { accH[ni][q] = 0; accL[ni][q] = 0; }

    // ---- preload chunks 0..2 ----
    #pragma unroll
    for (int p = 0; p < 3; ++p) {
        uint32_t dst = sbase + p * STAGE;
        CP_ASYNC16(dst + aSw, gXa + p * BK);
        CP_ASYNC16(dst + OFF_BW + bSw0, gW0 + p * BK);
        CP_ASYNC16(dst + OFF_BW + bSw1, gW1 + p * BK);
        CP_COMMIT();
    }

    for (int kc = 0; kc < NCH; ++kc) {
        const int s = kc & 3;
        if (kc < NCH - 2)       { CP_WAIT(2); }
        else if (kc == NCH - 2) { CP_WAIT(1); }
        else                    { CP_WAIT(0); }
        __syncthreads();

        if (kc + 3 < NCH) {
            uint32_t dst = sbase + ((kc + 3) & 3) * STAGE;
            CP_ASYNC16(dst + aSw, gXa + (kc + 3) * BK);
            CP_ASYNC16(dst + OFF_BW + bSw0, gW0 + (kc + 3) * BK);
            CP_ASYNC16(dst + OFF_BW + bSw1, gW1 + (kc + 3) * BK);
            CP_COMMIT();
        }

        const uint32_t base = sbase + s * STAGE;
        #pragma unroll
        for (int ks = 0; ks < 2; ++ks) {
            uint32_t ah[4], al[4], bb[4][2];
            #pragma unroll
            for (int n2 = 0; n2 < 2; ++n2)
                ldm_x4(bb[2 * n2][0], bb[2 * n2][1], bb[2 * n2 + 1][0], bb[2 * n2 + 1][1],
                       base + OFF_BW + bOff[n2][ks]);
            ldm_x4(ah[0], ah[1], ah[2], ah[3], base + aOff[ks]);
            ldm_x4(al[0], al[1], al[2], al[3], base + OFF_ALO + aOff[ks]);

            #pragma unroll
            for (int ni = 0; ni < 4; ++ni) {
                MMA_S8(accH[ni], ah, bb[ni]);
                MMA_S8(accL[ni], al, bb[ni]);
            }
        }
    }

    // ---- epilogue: combine planes, bias + hardtanh, fused fc2 ----
    const int dg = lane >> 2;
    const int dt = lane & 3;

    float hv[4][4];
    #pragma unroll
    for (int ni = 0; ni < 4; ++ni)
        #pragma unroll
        for (int q = 0; q < 4; ++q) {
            int n = wn * 32 + ni * 8 + 2 * dt + (q & 1);
            float hf = fmaf(256.0f, (float)accH[ni][q], (float)accL[ni][q]);
            float v  = fmaf(hf, INV_S, b1s[n]);
            hv[ni][q] = fminf(1.0f, fmaxf(-1.0f, v));
        }

    #pragma unroll
    for (int o = 0; o < NOUT; ++o) {
        float s0 = 0.0f, s1 = 0.0f;
        #pragma unroll
        for (int ni = 0; ni < 4; ++ni) {
            int n0 = wn * 32 + ni * 8 + 2 * dt;
            float w0 = W2s[o * BN + n0];
            float w1 = W2s[o * BN + n0 + 1];
            s0 = fmaf(hv[ni][0], w0, fmaf(hv[ni][1], w1, s0));
            s1 = fmaf(hv[ni][2], w0, fmaf(hv[ni][3], w1, s1));
        }
        s0 += __shfl_xor_sync(0xffffffffu, s0, 1);
        s0 += __shfl_xor_sync(0xffffffffu, s0, 2);
        s1 += __shfl_xor_sync(0xffffffffu, s1, 1);
        s1 += __shfl_xor_sync(0xffffffffu, s1, 2);
        if (dt == 0) {
            int r0 = bm + wm * 16 + dg;
            atomicAdd(&out[(size_t)r0 * NOUT + o], s0);
            atomicAdd(&out[(size_t)(r0 + 8) * NOUT + o], s1);
        }
    }
}

// ---------------------------------------------------------------- launch
extern "C" void kernel_launch(void* const* d_in, const int* in_sizes, int n_in,
                              void* d_out, int out_size) {
    const float* X  = (const float*)d_in[0];   // [8192, 784]
    const float* W1 = (const float*)d_in[1];   // [4096, 784]
    const float* b1 = (const float*)d_in[2];   // [4096]
    const float* W2 = (const float*)d_in[3];   // [10, 4096]
    const float* b2 = (const float*)d_in[4];   // [10]
    float* out = (float*)d_out;                // [8192, 10]
    (void)in_sizes; (void)n_in; (void)out_size;

    cudaFuncSetAttribute(fused_i8_kernel,
                         cudaFuncAttributeMaxDynamicSharedMemorySize, SMEM_REQ);

    init_out_kernel<<<(BATCH * NOUT + 255) / 256, 256>>>(out, b2);
    conv_x8_kernel<<<(BATCH * (KP8 / 4) + 255) / 256, 256>>>(X);
    conv_w8_kernel<<<(HID * (KP8 / 4) + 255) / 256, 256>>>(W1);

    dim3 grid(HID / BN, BATCH / BM);   // (32, 256) = 8192 CTAs
    fused_i8_kernel<<<grid, 256, SMEM_REQ>>>(b1, W2, out);
}

// round 9
// speedup vs baseline: 1.1429x; 1.1429x over previous
#include <cuda_runtime.h>
#include <cstdint>

// CovNet_3058016715001 — binarized-weight MLP via int8 dual-plane mma.sync.
// Round 9: round-7 shape (BM64 BN128, 8 warps m32n32, 2 CTAs/SM) with
// paired chunks per barrier (7 barriers) and a 6-stage cp.async ring.
//   h   = clip(x @ sign(W1)^T + b1, -1, 1)     x:[8192,784] W1:[4096,784]
//   out = h @ W2^T + b2                        W2:[10,4096]  out:[8192,10]
//
// x -> Q = round(x*4096) = 256*Qh + Ql (two s8 planes); sign(W1) exact s8.
// Dual s32 accumulators; epilogue h = (256*accH + accL)/4096 + b1 -> clip
// -> fused fc2 -> atomicAdd (out pre-seeded with b2).

#define BATCH 8192
#define IN_F  784
#define KP8   832           // 13 * 64
#define HID   4096
#define NOUT  10

#define BM 64
#define BN 128
#define BK 64
#define NCH 13
#define NSTG 6

// stage layout: A_hi [64x64]=4K | A_lo 4K | B [128x64]=8K
#define OFF_ALO 4096
#define OFF_BW  8192
#define STAGE   16384

// dynamic smem map (128-aligned base):
//   [0, 98304)        6 stages
//   [98304, 103424)   W2s [10][128] f32
//   [103424, 103936)  b1s [128] f32
#define OFF_W2   98304
#define OFF_B1   103424
#define SMEM_REQ (103936 + 128)

#define SCALE_S 4096.0f
#define INV_S   (1.0f / 4096.0f)

static __device__ char g_Xh8[(size_t)BATCH * KP8];
static __device__ char g_Xl8[(size_t)BATCH * KP8];
static __device__ char g_W8 [(size_t)HID * KP8];

// ---------------------------------------------------------------- helpers
__device__ __forceinline__ uint32_t smem_u32(const void* p) {
    return (uint32_t)__cvta_generic_to_shared(p);
}

#define CP_ASYNC16(s, g) \
    asm volatile("cp.async.cg.shared.global [%0], [%1], 16;" :: "r"(s), "l"(g))
#define CP_COMMIT() asm volatile("cp.async.commit_group;")
#define CP_WAIT(n)  asm volatile("cp.async.wait_group %0;" :: "n"(n) : "memory")

__device__ __forceinline__ void ldm_x4(uint32_t& r0, uint32_t& r1, uint32_t& r2,
                                       uint32_t& r3, uint32_t addr) {
    asm volatile("ldmatrix.sync.aligned.m8n8.x4.shared.b16 {%0,%1,%2,%3}, [%4];"
                 : "=r"(r0), "=r"(r1), "=r"(r2), "=r"(r3) : "r"(addr));
}

#define MMA_S8(d, a, b) \
    asm volatile("mma.sync.aligned.m16n8k32.row.col.s32.s8.s8.s32 " \
        "{%0,%1,%2,%3}, {%4,%5,%6,%7}, {%8,%9}, {%0,%1,%2,%3};" \
        : "+r"((d)[0]), "+r"((d)[1]), "+r"((d)[2]), "+r"((d)[3]) \
        : "r"((a)[0]), "r"((a)[1]), "r"((a)[2]), "r"((a)[3]), \
          "r"((b)[0]), "r"((b)[1]))

__device__ __forceinline__ uint32_t sw128(uint32_t flat) {
    return flat ^ ((flat >> 3) & 0x70);
}

// ---------------------------------------------------------------- prep
__global__ void init_out_kernel(float* __restrict__ out, const float* __restrict__ b2) {
    int i = blockIdx.x * blockDim.x + threadIdx.x;
    if (i < BATCH * NOUT) out[i] = b2[i % NOUT];
}

__global__ void conv_x8_kernel(const float* __restrict__ X) {
    int idx = blockIdx.x * blockDim.x + threadIdx.x;
    if (idx >= BATCH * (KP8 / 4)) return;
    int r  = idx / (KP8 / 4);
    int c4 = (idx % (KP8 / 4)) * 4;
    char hq[4], lq[4];
    #pragma unroll
    for (int j = 0; j < 4; ++j) {
        int col = c4 + j;
        float x = (col < IN_F) ? X[(size_t)r * IN_F + col] : 0.0f;
        int Q = __float2int_rn(x * SCALE_S);
        Q = max(-32512, min(32512, Q));
        int Qh = (Q + 128) >> 8;
        int Ql = Q - (Qh << 8);
        hq[j] = (char)Qh;
        lq[j] = (char)Ql;
    }
    *(char4*)(g_Xh8 + (size_t)r * KP8 + c4) = make_char4(hq[0], hq[1], hq[2], hq[3]);
    *(char4*)(g_Xl8 + (size_t)r * KP8 + c4) = make_char4(lq[0], lq[1], lq[2], lq[3]);
}

__global__ void conv_w8_kernel(const float* __restrict__ W1) {
    int idx = blockIdx.x * blockDim.x + threadIdx.x;
    if (idx >= HID * (KP8 / 4)) return;
    int r  = idx / (KP8 / 4);
    int c4 = (idx % (KP8 / 4)) * 4;
    char s[4];
    #pragma unroll
    for (int j = 0; j < 4; ++j) {
        int col = c4 + j;
        char v = 0;
        if (col < IN_F) {
            float w = W1[(size_t)r * IN_F + col];
            v = (w > 0.0f) ? (char)1 : ((w < 0.0f) ? (char)-1 : (char)0);
        }
        s[j] = v;
    }
    *(char4*)(g_W8 + (size_t)r * KP8 + c4) = make_char4(s[0], s[1], s[2], s[3]);
}

// ---------------------------------------------------------------- main
__global__ void __launch_bounds__(256, 2) fused_i8_kernel(
    const float* __restrict__ b1, const float* __restrict__ W2,
    float* __restrict__ out)
{
    extern __shared__ char smem_raw[];
    const uint32_t rawA  = smem_u32(smem_raw);
    const uint32_t sbase = (rawA + 127) & ~127u;
    char* gbase = smem_raw + (sbase - rawA);
    float* W2s = (float*)(gbase + OFF_W2);
    float* b1s = (float*)(gbase + OFF_B1);

    const int tid  = threadIdx.x;
    const int lane = tid & 31;
    const int wid  = tid >> 5;
    const int wm   = wid & 1;        // 2 warps along M (32 rows each)
    const int wn   = wid >> 1;       // 4 warps along N (32 cols each)

    const int bm = blockIdx.y * BM;
    const int bn = blockIdx.x * BN;

    // ---- stage W2 / b1 slices (used only in epilogue) ----
    for (int i = tid; i < NOUT * BN; i += 256)
        W2s[i] = W2[(size_t)(i >> 7) * HID + bn + (i & 127)];
    if (tid < BN) b1s[tid] = b1[bn + tid];

    // ---- loader mapping (per chunk: Ahi, Alo, B0, B1 = 4 x 16B / thread) ----
    const int lrow = tid >> 2;           // 0..63
    const int lseg = tid & 3;
    const uint32_t aSw  = sw128((uint32_t)tid * 16);
    const uint32_t bSw0 = aSw;
    const uint32_t bSw1 = sw128((uint32_t)tid * 16 + 4096);
    const char* gXh = g_Xh8 + (size_t)(bm + lrow) * KP8 + lseg * 16;
    const char* gXl = g_Xl8 + (size_t)(bm + lrow) * KP8 + lseg * 16;
    const char* gW0 = g_W8  + (size_t)(bn + lrow) * KP8 + lseg * 16;
    const char* gW1 = g_W8  + (size_t)(bn + 64 + lrow) * KP8 + lseg * 16;

    // ---- ldmatrix per-lane offsets (row stride 64 B, 2 k-steps) ----
    const int lg  = lane >> 3;
    const int lr8 = lane & 7;
    uint32_t aOff[2][2], bOff[2][2];
    #pragma unroll
    for (int mi = 0; mi < 2; ++mi) {
        int r = wm * 32 + mi * 16 + ((lg & 1) << 3) + lr8;
        #pragma unroll
        for (int ks = 0; ks < 2; ++ks)
            aOff[mi][ks] = sw128((uint32_t)(r * 64 + ks * 32 + (lg >> 1) * 16));
    }
    #pragma unroll
    for (int n2 = 0; n2 < 2; ++n2) {
        int r = wn * 32 + n2 * 16 + (((lane >> 4) & 1) << 3) + lr8;
        #pragma unroll
        for (int ks = 0; ks < 2; ++ks)
            bOff[n2][ks] = sw128((uint32_t)(r * 64 + ks * 32 + (lg & 1) * 16));
    }

    int accH[2][4][4], accL[2][4][4];
    #pragma unroll
    for (int mi = 0; mi < 2; ++mi)
        #pragma unroll
        for (int ni = 0; ni < 4; ++ni)
            #pragma unroll
            for (int q = 0; q < 4; ++q) { accH[mi][ni][q] = 0; accL[mi][ni][q] = 0; }

    // ---- issue loads for one chunk into its stage ----
    #define LOAD_CHUNK(c) do {                                             \
        uint32_t dst_ = sbase + (uint32_t)((c) % NSTG) * STAGE;            \
        CP_ASYNC16(dst_ + aSw,            gXh + (c) * BK);                 \
        CP_ASYNC16(dst_ + OFF_ALO + aSw,  gXl + (c) * BK);                 \
        CP_ASYNC16(dst_ + OFF_BW + bSw0,  gW0 + (c) * BK);                 \
        CP_ASYNC16(dst_ + OFF_BW + bSw1,  gW1 + (c) * BK);                 \
    } while (0)

    // ---- consume one chunk's stage ----
    #define COMPUTE_CHUNK(c) do {                                          \
        const uint32_t base_ = sbase + (uint32_t)((c) % NSTG) * STAGE;     \
        _Pragma("unroll")                                                  \
        for (int ks = 0; ks < 2; ++ks) {                                   \
            uint32_t ah[2][4], al[2][4], bb[4][2];                         \
            _Pragma("unroll")                                              \
            for (int n2 = 0; n2 < 2; ++n2)                                 \
                ldm_x4(bb[2*n2][0], bb[2*n2][1], bb[2*n2+1][0],            \
                       bb[2*n2+1][1], base_ + OFF_BW + bOff[n2][ks]);      \
            _Pragma("unroll")                                              \
            for (int mi = 0; mi < 2; ++mi)                                 \
                ldm_x4(ah[mi][0], ah[mi][1], ah[mi][2], ah[mi][3],         \
                       base_ + aOff[mi][ks]);                              \
            _Pragma("unroll")                                              \
            for (int mi = 0; mi < 2; ++mi)                                 \
                ldm_x4(al[mi][0], al[mi][1], al[mi][2], al[mi][3],         \
                       base_ + OFF_ALO + aOff[mi][ks]);                    \
            _Pragma("unroll")                                              \
            for (int mi = 0; mi < 2; ++mi)                                 \
                _Pragma("unroll")                                          \
                for (int ni = 0; ni < 4; ++ni) {                           \
                    MMA_S8(accH[mi][ni], ah[mi], bb[ni]);                  \
                    MMA_S8(accL[mi][ni], al[mi], bb[ni]);                  \
                }                                                          \
        }                                                                  \
    } while (0)

    // ---- preload pairs 0 (c0,c1) and 1 (c2,c3): one commit group each ----
    LOAD_CHUNK(0); LOAD_CHUNK(1); CP_COMMIT();
    LOAD_CHUNK(2); LOAD_CHUNK(3); CP_COMMIT();

    // ---- main loop: 6 pairs + 1 tail chunk (13 chunks total) ----
    for (int p = 0; p < 6; ++p) {
        CP_WAIT(1);                 // pair p complete (pair p+1 may still fly)
        __syncthreads();

        // prefetch pair p+2 (stages disjoint from pairs p and p+1 in the 6-ring)
        if (p < 5) {
            LOAD_CHUNK(2 * p + 4);
            LOAD_CHUNK(2 * p + 5);
        } else {
            LOAD_CHUNK(12);
        }
        CP_COMMIT();

        COMPUTE_CHUNK(2 * p);
        COMPUTE_CHUNK(2 * p + 1);
    }

    CP_WAIT(0);
    __syncthreads();
    COMPUTE_CHUNK(12);

    #undef LOAD_CHUNK
    #undef COMPUTE_CHUNK

    // ---- epilogue: combine planes, bias + hardtanh, fused fc2 ----
    const int dg = lane >> 2;
    const int dt = lane & 3;

    float hv[2][4][4];
    #pragma unroll
    for (int mi = 0; mi < 2; ++mi)
        #pragma unroll
        for (int ni = 0; ni < 4; ++ni)
            #pragma unroll
            for (int q = 0; q < 4; ++q) {
                int n = wn * 32 + ni * 8 + 2 * dt + (q & 1);
                float hf = fmaf(256.0f, (float)accH[mi][ni][q], (float)accL[mi][ni][q]);
                float v  = fmaf(hf, INV_S, b1s[n]);
                hv[mi][ni][q] = fminf(1.0f, fmaxf(-1.0f, v));
            }

    #pragma unroll
    for (int o = 0; o < NOUT; ++o) {
        #pragma unroll
        for (int mi = 0; mi < 2; ++mi) {
            float s0 = 0.0f, s1 = 0.0f;
            #pragma unroll
            for (int ni = 0; ni < 4; ++ni) {
                int n0 = wn * 32 + ni * 8 + 2 * dt;
                float w0 = W2s[o * BN + n0];
                float w1 = W2s[o * BN + n0 + 1];
                s0 = fmaf(hv[mi][ni][0], w0, fmaf(hv[mi][ni][1], w1, s0));
                s1 = fmaf(hv[mi][ni][2], w0, fmaf(hv[mi][ni][3], w1, s1));
            }
            s0 += __shfl_xor_sync(0xffffffffu, s0, 1);
            s0 += __shfl_xor_sync(0xffffffffu, s0, 2);
            s1 += __shfl_xor_sync(0xffffffffu, s1, 1);
            s1 += __shfl_xor_sync(0xffffffffu, s1, 2);
            if (dt == 0) {
                int r0 = bm + wm * 32 + mi * 16 + dg;
                atomicAdd(&out[(size_t)r0 * NOUT + o], s0);
                atomicAdd(&out[(size_t)(r0 + 8) * NOUT + o], s1);
            }
        }
    }
}

// ---------------------------------------------------------------- launch
extern "C" void kernel_launch(void* const* d_in, const int* in_sizes, int n_in,
                              void* d_out, int out_size) {
    const float* X  = (const float*)d_in[0];   // [8192, 784]
    const float* W1 = (const float*)d_in[1];   // [4096, 784]
    const float* b1 = (const float*)d_in[2];   // [4096]
    const float* W2 = (const float*)d_in[3];   // [10, 4096]
    const float* b2 = (const float*)d_in[4];   // [10]
    float* out = (float*)d_out;                // [8192, 10]
    (void)in_sizes; (void)n_in; (void)out_size;

    cudaFuncSetAttribute(fused_i8_kernel,
                         cudaFuncAttributeMaxDynamicSharedMemorySize, SMEM_REQ);

    init_out_kernel<<<(BATCH * NOUT + 255) / 256, 256>>>(out, b2);
    conv_x8_kernel<<<(BATCH * (KP8 / 4) + 255) / 256, 256>>>(X);
    conv_w8_kernel<<<(HID * (KP8 / 4) + 255) / 256, 256>>>(W1);

    dim3 grid(HID / BN, BATCH / BM);   // (32, 128) = 4096 CTAs
    fused_i8_kernel<<<grid, 256, SMEM_REQ>>>(b1, W2, out);
}